// round 7
// baseline (speedup 1.0000x reference)
#include <cuda_runtime.h>
#include <math.h>

#define HW     16384
#define NCH    512
#define NC     16       // classes per group (C)
#define NG     32       // groups (G)
#define NB     8        // batch
#define NPAIR  120      // C*(C-1)/2
#define NBG    256      // NB*NG
#define NSEG   8        // HW segments per (b,g)
#define SEG    (HW / NSEG)      // 2048 floats per channel per segment
#define TILE   256      // floats per channel per pipeline tile (1 KB)
#define NT     (SEG / TILE)     // 8 tiles per segment
#define STAGES 6
#define DEPTH  4                // tiles in flight (64 KB per CTA)
#define STAGE_FLOATS (NC * TILE)                   // 4096 floats = 16 KB
#define SMEM_BYTES   (STAGES * STAGE_FLOATS * 4)   // 96 KB dynamic per CTA

// Device-global scratch (no allocations allowed)
__device__ int      g_chan[NG][NC];           // channel id: rank-g pick of class c
__device__ float    g_wgt[NG][NC];            // sigmoid(|w|) of that pick
__device__ float    g_S[NBG][NSEG][NPAIR];    // per-segment raw Gram partials
__device__ float    g_total;                  // accumulated loss (zero-init, restored)
__device__ unsigned g_count;                  // finalize completion counter

// ---------------------------------------------------------------------------
// Kernel A: selection via rank counting.
// grid = (16 classes, 8 channel-chunks), 512 threads.
// Slices are INTERLEAVED (k = sl + 8m) -> 8 distinct banks per warp,
// conflict-free LDS (the old blocked k0=sl*64 layout was an 8-way conflict).
// rank(i) = #{k : w_k > w_i or (w_k == w_i and k < i)} -> stable argsort(-w).
// ---------------------------------------------------------------------------
__global__ void select_kernel(const float* __restrict__ cw) {
    __shared__ float sw[NCH];
    const int j   = blockIdx.x;          // class
    const int q   = blockIdx.y;          // channel chunk (8 x 64)
    const int tid = threadIdx.x;
    sw[tid] = fabsf(cw[j * NCH + tid]);
    __syncthreads();

    const int chl = tid >> 3;            // 0..63 channel-in-chunk
    const int sl  = tid & 7;             // compare slice
    const int i   = q * 64 + chl;        // global channel
    const float wi = sw[i];

    int r = 0;
    #pragma unroll 8
    for (int m = 0; m < 64; m++) {
        const int k = sl + (m << 3);     // interleaved: conflict-free
        const float wk = sw[k];
        r += (wk > wi) || (wk == wi && k < i);
    }
    r += __shfl_xor_sync(0xffffffffu, r, 1);
    r += __shfl_xor_sync(0xffffffffu, r, 2);
    r += __shfl_xor_sync(0xffffffffu, r, 4);

    if (sl == 0 && r < NG) {
        g_chan[r][j] = i;
        g_wgt[r][j]  = 1.0f / (1.0f + expf(-wi));
    }
}

// ---------------------------------------------------------------------------
// Kernel B: Gram accumulation. 256 threads, 2 CTAs/SM, 6-stage depth-4
// cp.async pipeline. grid = 2048 = (bg 0..255) x (segment 0..7)
// (eighth-segments -> 6.9 waves, ~1% tail vs 13% at quarters).
//   loader role:  channel mc = tid>>4; 16 threads/channel, 64 B each.
//   compute role: grp = tid>>7 picks pair-half [0,60)/[60,120);
//                 lt2 = tid&127 is the float2 position in the tile.
// ---------------------------------------------------------------------------
template <int P0>
__device__ __forceinline__ void do_pairs60(const float2* __restrict__ v,
                                           float* __restrict__ acc) {
    int p = 0;
    #pragma unroll
    for (int c = 0; c < NC; c++) {
        #pragma unroll
        for (int d = c + 1; d < NC; d++) {
            if (p >= P0 && p < P0 + 60) {
                acc[p - P0] = fmaf(v[c].x, v[d].x,
                              fmaf(v[c].y, v[d].y, acc[p - P0]));
            }
            p++;
        }
    }
}

__global__ __launch_bounds__(256, 2) void gram_kernel(const float* __restrict__ x) {
    extern __shared__ __align__(16) float s_buf[];   // [STAGES][NC][TILE]

    const int bid = blockIdx.x;
    const int e   = bid & 7;             // segment
    const int bg  = bid >> 3;
    const int b   = bg >> 5;
    const int g   = bg & 31;
    const int tid = threadIdx.x;

    // loader role: 16 threads per channel
    const int mc = tid >> 4;             // channel 0..15
    const int ms = tid & 15;             // float4 slot within channel slice
    const float* src = x + ((size_t)(b * NCH + g_chan[g][mc])) * HW + e * SEG;

    // compute role
    const int grp  = tid >> 7;           // pair half: [0,60) or [60,120)
    const int lt2  = tid & 127;          // float2 position in tile
    const int warp = tid >> 5;
    const int lane = tid & 31;

    auto issue = [&](int t) {
        const int stage = t % STAGES;
        const float4* gp = reinterpret_cast<const float4*>(src + t * TILE) + ms;
        float4* sp = reinterpret_cast<float4*>(
                         &s_buf[stage * STAGE_FLOATS + mc * TILE]) + ms;
        #pragma unroll
        for (int k = 0; k < 4; k++) {
            unsigned sa = (unsigned)__cvta_generic_to_shared(sp + 16 * k);
            asm volatile("cp.async.cg.shared.global [%0], [%1], 16;\n"
                         :: "r"(sa), "l"(gp + 16 * k) : "memory");
        }
        asm volatile("cp.async.commit_group;" ::: "memory");
    };

    float acc[60];
    #pragma unroll
    for (int p = 0; p < 60; p++) acc[p] = 0.0f;

    // prologue: DEPTH tiles in flight
    #pragma unroll
    for (int t = 0; t < DEPTH; t++) issue(t);

    for (int t = 0; t < NT; t++) {
        asm volatile("cp.async.wait_group %0;" :: "n"(DEPTH - 1) : "memory");
        __syncthreads();                 // tile t visible; oldest stage free

        const float2* sm = reinterpret_cast<const float2*>(
                               &s_buf[(t % STAGES) * STAGE_FLOATS]);
        float2 v[NC];
        #pragma unroll
        for (int c = 0; c < NC; c++) v[c] = sm[c * (TILE / 2) + lt2];

        if (grp == 0) do_pairs60<0 >(v, acc);
        else          do_pairs60<60>(v, acc);

        if (t + DEPTH < NT) issue(t + DEPTH);
    }

    asm volatile("cp.async.wait_group 0;" ::: "memory");
    __syncthreads();

    // cross-warp reduce: butterfly -> smem partials [8 warps][60]
    float* s_part = s_buf;
    #pragma unroll
    for (int p = 0; p < 60; p++) {
        float vv = acc[p];
        vv += __shfl_xor_sync(0xffffffffu, vv, 16);
        vv += __shfl_xor_sync(0xffffffffu, vv, 8);
        vv += __shfl_xor_sync(0xffffffffu, vv, 4);
        vv += __shfl_xor_sync(0xffffffffu, vv, 2);
        vv += __shfl_xor_sync(0xffffffffu, vv, 1);
        if (lane == 0) s_part[warp * 60 + p] = vv;
    }
    __syncthreads();

    // pair-half h used warps [h*4, h*4+4)
    if (tid < NPAIR) {
        const int h  = tid / 60;
        const int pp = tid % 60;
        float s = 0.0f;
        #pragma unroll
        for (int w = 0; w < 4; w++) s += s_part[(h * 4 + w) * 60 + pp];
        g_S[bg][e][tid] = s;
    }
}

// ---------------------------------------------------------------------------
// Kernel C: per-(b,g) weighted |cov| + margin + clamp, then single-pass
// global accumulate; the LAST block writes the output and restores the
// counters (invariant re-established every call -> graph-replay safe).
// grid = 256 blocks (one per bg), 128 threads (threads 0..119 own pair p).
// ---------------------------------------------------------------------------
__global__ void finalize_kernel(float* __restrict__ out) {
    __shared__ float s_red[4];
    const int bg  = blockIdx.x;
    const int g   = bg & 31;
    const int p   = threadIdx.x;         // pair id (0..119 active)
    const int warp = p >> 5;
    const int lane = p & 31;

    float val = 0.0f;
    if (p < NPAIR) {
        // decode pair p -> (c, d)
        int c = 0, rem = p;
        #pragma unroll
        for (int cc = 0; cc < NC - 1; cc++) {
            const int row = NC - 1 - cc;      // pairs in row cc
            if (rem >= row && c == cc) { rem -= row; c = cc + 1; }
        }
        const int d = c + 1 + rem;

        float S = 0.0f;
        #pragma unroll
        for (int s = 0; s < NSEG; s++) S += g_S[bg][s][p];
        val = g_wgt[g][c] * g_wgt[g][d] * fabsf(S);
    }

    val += __shfl_xor_sync(0xffffffffu, val, 16);
    val += __shfl_xor_sync(0xffffffffu, val, 8);
    val += __shfl_xor_sync(0xffffffffu, val, 4);
    val += __shfl_xor_sync(0xffffffffu, val, 2);
    val += __shfl_xor_sync(0xffffffffu, val, 1);
    if (lane == 0) s_red[warp] = val;
    __syncthreads();

    if (p == 0) {
        const float tot = s_red[0] + s_red[1] + s_red[2] + s_red[3];
        const float sum_abs_cov = tot / (float)(HW - 1);
        const float off_diag    = sum_abs_cov - 60.0f;   // margin = floor(120/2)
        const float loss        = fmaxf(off_diag / 120.0f, 0.0f);

        atomicAdd(&g_total, loss);
        __threadfence();
        const unsigned old = atomicAdd(&g_count, 1u);
        if (old == NBG - 1) {
            // all 256 adds are visible (each block fenced before counting)
            const float t = atomicAdd(&g_total, 0.0f);   // atomic read
            out[0] = t / (float)NB;
            g_total = 0.0f;              // restore invariant for next replay
            g_count = 0u;
            __threadfence();
        }
    }
}

// ---------------------------------------------------------------------------
extern "C" void kernel_launch(void* const* d_in, const int* in_sizes, int n_in,
                              void* d_out, int out_size) {
    (void)in_sizes; (void)n_in; (void)out_size;
    const float* x  = (const float*)d_in[0];   // [8,512,128,128] fp32
    const float* cw = (const float*)d_in[1];   // [19,512] fp32

    cudaFuncSetAttribute(gram_kernel,
                         cudaFuncAttributeMaxDynamicSharedMemorySize,
                         SMEM_BYTES);

    select_kernel<<<dim3(16, 8), 512>>>(cw);
    gram_kernel<<<NBG * NSEG, 256, SMEM_BYTES>>>(x);
    finalize_kernel<<<NBG, 128>>>((float*)d_out);
}

// round 8
// speedup vs baseline: 1.7645x; 1.7645x over previous
#include <cuda_runtime.h>
#include <math.h>

#define HW     16384
#define NCH    512
#define NC     16       // classes per group (C)
#define NG     32       // groups (G)
#define NB     8        // batch
#define NPAIR  120      // C*(C-1)/2
#define NBG    256      // NB*NG
#define QTR    4096     // floats per channel per quarter of HW
#define TILE   256      // floats per channel per pipeline tile (1 KB)
#define NT     (QTR / TILE)     // 16 tiles per quarter
#define STAGES 6
#define DEPTH  4                // tiles in flight (64 KB per CTA)
#define STAGE_FLOATS (NC * TILE)                   // 4096 floats = 16 KB
#define SMEM_BYTES   (STAGES * STAGE_FLOATS * 4)   // 96 KB dynamic per CTA

// Device-global scratch (no allocations allowed)
__device__ int   g_chan[NG][NC];          // channel id: rank-g pick of class c
__device__ float g_wgt[NG][NC];           // sigmoid(|w|) of that pick
__device__ float g_S4[NBG][4][NPAIR];     // per-quarter raw Gram partials
__device__ float g_loss[NBG];             // per-(b,g) clamped loss

// ---------------------------------------------------------------------------
// Kernel A: selection via rank counting.
// grid = (16 classes, 8 channel-chunks), 512 threads.
// Slices INTERLEAVED (k = sl + 8m): 8 distinct banks per warp -> conflict-free
// LDS (measured: 8.3us blocked -> 7.1us interleaved, issue 17.6% -> 55.7%).
// rank(i) = #{k : w_k > w_i or (w_k == w_i and k < i)} -> stable argsort(-w).
// ---------------------------------------------------------------------------
__global__ void select_kernel(const float* __restrict__ cw) {
    __shared__ float sw[NCH];
    const int j   = blockIdx.x;          // class
    const int q   = blockIdx.y;          // channel chunk (8 x 64)
    const int tid = threadIdx.x;
    sw[tid] = fabsf(cw[j * NCH + tid]);
    __syncthreads();

    const int chl = tid >> 3;            // 0..63 channel-in-chunk
    const int sl  = tid & 7;             // compare slice
    const int i   = q * 64 + chl;        // global channel
    const float wi = sw[i];

    int r = 0;
    #pragma unroll 8
    for (int m = 0; m < 64; m++) {
        const int k = sl + (m << 3);     // interleaved: conflict-free
        const float wk = sw[k];
        r += (wk > wi) || (wk == wi && k < i);
    }
    r += __shfl_xor_sync(0xffffffffu, r, 1);
    r += __shfl_xor_sync(0xffffffffu, r, 2);
    r += __shfl_xor_sync(0xffffffffu, r, 4);

    if (sl == 0 && r < NG) {
        g_chan[r][j] = i;
        g_wgt[r][j]  = 1.0f / (1.0f + expf(-wi));
    }
}

// ---------------------------------------------------------------------------
// Kernel B: Gram accumulation (R6 known-good config). 256 threads, 2 CTAs/SM,
// 6-stage depth-4 cp.async pipeline. grid = 1024 = (bg 0..255) x (quarter).
//   loader role:  channel mc = tid>>4; 16 threads/channel, 64 B each.
//   compute role: grp = tid>>7 picks pair-half [0,60)/[60,120);
//                 lt2 = tid&127 is the float2 position in the tile.
// ---------------------------------------------------------------------------
template <int P0>
__device__ __forceinline__ void do_pairs60(const float2* __restrict__ v,
                                           float* __restrict__ acc) {
    int p = 0;
    #pragma unroll
    for (int c = 0; c < NC; c++) {
        #pragma unroll
        for (int d = c + 1; d < NC; d++) {
            if (p >= P0 && p < P0 + 60) {
                acc[p - P0] = fmaf(v[c].x, v[d].x,
                              fmaf(v[c].y, v[d].y, acc[p - P0]));
            }
            p++;
        }
    }
}

__global__ __launch_bounds__(256, 2) void gram_kernel(const float* __restrict__ x) {
    extern __shared__ __align__(16) float s_buf[];   // [STAGES][NC][TILE]

    const int bid = blockIdx.x;
    const int q   = bid & 3;             // quarter
    const int bg  = bid >> 2;
    const int b   = bg >> 5;
    const int g   = bg & 31;
    const int tid = threadIdx.x;

    // loader role: 16 threads per channel
    const int mc = tid >> 4;             // channel 0..15
    const int ms = tid & 15;             // float4 slot within channel slice
    const float* src = x + ((size_t)(b * NCH + g_chan[g][mc])) * HW + q * QTR;

    // compute role
    const int grp  = tid >> 7;           // pair half: [0,60) or [60,120)
    const int lt2  = tid & 127;          // float2 position in tile
    const int warp = tid >> 5;
    const int lane = tid & 31;

    auto issue = [&](int t) {
        const int stage = t % STAGES;
        const float4* gp = reinterpret_cast<const float4*>(src + t * TILE) + ms;
        float4* sp = reinterpret_cast<float4*>(
                         &s_buf[stage * STAGE_FLOATS + mc * TILE]) + ms;
        #pragma unroll
        for (int k = 0; k < 4; k++) {
            unsigned sa = (unsigned)__cvta_generic_to_shared(sp + 16 * k);
            asm volatile("cp.async.cg.shared.global [%0], [%1], 16;\n"
                         :: "r"(sa), "l"(gp + 16 * k) : "memory");
        }
        asm volatile("cp.async.commit_group;" ::: "memory");
    };

    float acc[60];
    #pragma unroll
    for (int p = 0; p < 60; p++) acc[p] = 0.0f;

    // prologue: DEPTH tiles in flight
    #pragma unroll
    for (int t = 0; t < DEPTH; t++) issue(t);

    for (int t = 0; t < NT; t++) {
        asm volatile("cp.async.wait_group %0;" :: "n"(DEPTH - 1) : "memory");
        __syncthreads();                 // tile t visible; oldest stage free

        const float2* sm = reinterpret_cast<const float2*>(
                               &s_buf[(t % STAGES) * STAGE_FLOATS]);
        float2 v[NC];
        #pragma unroll
        for (int c = 0; c < NC; c++) v[c] = sm[c * (TILE / 2) + lt2];

        if (grp == 0) do_pairs60<0 >(v, acc);
        else          do_pairs60<60>(v, acc);

        if (t + DEPTH < NT) issue(t + DEPTH);
    }

    asm volatile("cp.async.wait_group 0;" ::: "memory");
    __syncthreads();

    // cross-warp reduce: butterfly -> smem partials [8 warps][60]
    float* s_part = s_buf;
    #pragma unroll
    for (int p = 0; p < 60; p++) {
        float vv = acc[p];
        vv += __shfl_xor_sync(0xffffffffu, vv, 16);
        vv += __shfl_xor_sync(0xffffffffu, vv, 8);
        vv += __shfl_xor_sync(0xffffffffu, vv, 4);
        vv += __shfl_xor_sync(0xffffffffu, vv, 2);
        vv += __shfl_xor_sync(0xffffffffu, vv, 1);
        if (lane == 0) s_part[warp * 60 + p] = vv;
    }
    __syncthreads();

    // pair-half h used warps [h*4, h*4+4)
    if (tid < NPAIR) {
        const int h  = tid / 60;
        const int pp = tid % 60;
        float s = 0.0f;
        #pragma unroll
        for (int w = 0; w < 4; w++) s += s_part[(h * 4 + w) * 60 + pp];
        g_S4[bg][q][tid] = s;
    }
}

// ---------------------------------------------------------------------------
// Kernel C1: per-(b,g) weighted |cov| + margin + clamp.
// grid = 256 blocks (one per bg), 128 threads (threads 0..119 own pair p).
// ---------------------------------------------------------------------------
__global__ void finalize1_kernel() {
    __shared__ float s_red[4];
    const int bg  = blockIdx.x;
    const int g   = bg & 31;
    const int p   = threadIdx.x;         // pair id (0..119 active)
    const int warp = p >> 5;
    const int lane = p & 31;

    float val = 0.0f;
    if (p < NPAIR) {
        // decode pair p -> (c, d)
        int c = 0, rem = p;
        #pragma unroll
        for (int cc = 0; cc < NC - 1; cc++) {
            const int row = NC - 1 - cc;      // pairs in row cc
            if (rem >= row && c == cc) { rem -= row; c = cc + 1; }
        }
        const int d = c + 1 + rem;

        const float S = g_S4[bg][0][p] + g_S4[bg][1][p] +
                        g_S4[bg][2][p] + g_S4[bg][3][p];
        val = g_wgt[g][c] * g_wgt[g][d] * fabsf(S);
    }

    val += __shfl_xor_sync(0xffffffffu, val, 16);
    val += __shfl_xor_sync(0xffffffffu, val, 8);
    val += __shfl_xor_sync(0xffffffffu, val, 4);
    val += __shfl_xor_sync(0xffffffffu, val, 2);
    val += __shfl_xor_sync(0xffffffffu, val, 1);
    if (lane == 0) s_red[warp] = val;
    __syncthreads();

    if (p == 0) {
        const float tot = s_red[0] + s_red[1] + s_red[2] + s_red[3];
        const float sum_abs_cov = tot / (float)(HW - 1);
        const float off_diag    = sum_abs_cov - 60.0f;   // margin = floor(120/2)
        g_loss[bg] = fmaxf(off_diag / 120.0f, 0.0f);
    }
}

// ---------------------------------------------------------------------------
// Kernel C2: sum 256 losses, divide by batch. 1 block, 256 threads.
// ---------------------------------------------------------------------------
__global__ void finalize2_kernel(float* __restrict__ out) {
    __shared__ float red[NBG];
    const int t = threadIdx.x;
    red[t] = g_loss[t];
    __syncthreads();
    for (int s = 128; s > 0; s >>= 1) {
        if (t < s) red[t] += red[t + s];
        __syncthreads();
    }
    if (t == 0) out[0] = red[0] / (float)NB;
}

// ---------------------------------------------------------------------------
extern "C" void kernel_launch(void* const* d_in, const int* in_sizes, int n_in,
                              void* d_out, int out_size) {
    (void)in_sizes; (void)n_in; (void)out_size;
    const float* x  = (const float*)d_in[0];   // [8,512,128,128] fp32
    const float* cw = (const float*)d_in[1];   // [19,512] fp32

    cudaFuncSetAttribute(gram_kernel,
                         cudaFuncAttributeMaxDynamicSharedMemorySize,
                         SMEM_BYTES);

    select_kernel<<<dim3(16, 8), 512>>>(cw);
    gram_kernel<<<1024, 256, SMEM_BYTES>>>(x);
    finalize1_kernel<<<NBG, 128>>>();
    finalize2_kernel<<<1, 256>>>((float*)d_out);
}